// round 14
// baseline (speedup 1.0000x reference)
#include <cuda_runtime.h>
#include <cstdint>
#include <math.h>

// Problem constants (shapes are fixed by the dataset)
#define BB 8
#define CC 64
#define NN 8192
#define MM 2048
#define KNNK 16
#define FPS_M 1433   // int(2048 * 0.7)
#define RAND_M 615   // 2048 - 1433

#define FT 256               // fused kernel block size (8 warps)
#define KNB (BB * 256)       // knn blocks (8 centers each)
#define INF64 0xFFFFFFFFFFFFFFFFull

// ---------------------------------------------------------------------------
// Threefry-2x32 core (jax threefry2x32 primitive)
// ---------------------------------------------------------------------------
__host__ __device__ __forceinline__ void threefry2x32(
    uint32_t k0, uint32_t k1, uint32_t c0, uint32_t c1,
    uint32_t* o0, uint32_t* o1) {
  uint32_t ks2 = 0x1BD11BDAu ^ k0 ^ k1;
  uint32_t x0 = c0 + k0;
  uint32_t x1 = c1 + k1;
#define TF_ROTL(v, r) (((v) << (r)) | ((v) >> (32 - (r))))
#define TF_ROUND(r) do { x0 += x1; x1 = TF_ROTL(x1, r); x1 ^= x0; } while (0)
  TF_ROUND(13); TF_ROUND(15); TF_ROUND(26); TF_ROUND(6);
  x0 += k1; x1 += ks2 + 1u;
  TF_ROUND(17); TF_ROUND(29); TF_ROUND(16); TF_ROUND(24);
  x0 += ks2; x1 += k0 + 2u;
  TF_ROUND(13); TF_ROUND(15); TF_ROUND(26); TF_ROUND(6);
  x0 += k0; x1 += k1 + 3u;
  TF_ROUND(17); TF_ROUND(29); TF_ROUND(16); TF_ROUND(24);
  x0 += k1; x1 += ks2 + 4u;
  TF_ROUND(13); TF_ROUND(15); TF_ROUND(26); TF_ROUND(6);
  x0 += ks2; x1 += k0 + 5u;
#undef TF_ROUND
#undef TF_ROTL
  *o0 = x0; *o1 = x1;
}

struct FpsArgs  { int start[BB]; };
struct PermArgs { uint32_t sub[BB][2][2]; };

__device__ int g_idx[BB * MM];
__device__ float4 g_pack[BB * NN];       // (x, y, z, ||p||^2) per point
__device__ volatile int g_prog[BB];      // # valid FPS entries in g_idx
__device__ volatile int g_permdone[BB];  // perm tail written flag

// ---------------------------------------------------------------------------
// Packed f32x2 helpers (bit-exact per-lane .rn semantics, sm_103a)
// ---------------------------------------------------------------------------
__device__ __forceinline__ unsigned long long f2_pack(float lo, float hi) {
  unsigned long long o;
  asm("mov.b64 %0, {%1, %2};" : "=l"(o) : "f"(lo), "f"(hi));
  return o;
}
__device__ __forceinline__ void f2_unpack(unsigned long long v, float* lo, float* hi) {
  asm("mov.b64 {%0, %1}, %2;" : "=f"(*lo), "=f"(*hi) : "l"(v));
}
__device__ __forceinline__ unsigned long long f2_add(unsigned long long a,
                                                     unsigned long long b) {
  unsigned long long o;
  asm("add.rn.f32x2 %0, %1, %2;" : "=l"(o) : "l"(a), "l"(b));
  return o;
}
__device__ __forceinline__ unsigned long long f2_mul(unsigned long long a,
                                                     unsigned long long b) {
  unsigned long long o;
  asm("mul.rn.f32x2 %0, %1, %2;" : "=l"(o) : "l"(a), "l"(b));
  return o;
}

// monotone map: float bits -> u32 preserving float ordering (handles negatives)
__device__ __forceinline__ uint32_t f2ord(float f) {
  uint32_t u = __float_as_uint(f);
  return u ^ ((u & 0x80000000u) ? 0xFFFFFFFFu : 0x80000000u);
}

// ---------------------------------------------------------------------------
// Host-side PRNG derivation — PARTITIONABLE threefry semantics
// ---------------------------------------------------------------------------
static void compute_consts(FpsArgs* fa, PermArgs* pa) {
  for (int b = 0; b < BB; b++) {
    uint32_t fk0, fk1;
    threefry2x32(0u, 42u, 0u, (uint32_t)b, &fk0, &fk1);
    uint32_t k20, k21;
    threefry2x32(fk0, fk1, 0u, 1u, &k20, &k21);
    uint32_t s0, s1;
    threefry2x32(k20, k21, 0u, 0u, &s0, &s1);
    fa->start[b] = (int)((s0 ^ s1) & (NN - 1));
  }
  uint32_t rk0, rk1;
  threefry2x32(0u, 42u, 0u, 1u, &rk0, &rk1);
  for (int b = 0; b < BB; b++) {
    uint32_t k0, k1;
    threefry2x32(rk0, rk1, 0u, (uint32_t)b, &k0, &k1);
    for (int r = 0; r < 2; r++) {
      uint32_t n0, n1, c0, c1;
      threefry2x32(k0, k1, 0u, 0u, &n0, &n1);
      threefry2x32(k0, k1, 0u, 1u, &c0, &c1);
      pa->sub[b][r][0] = c0;
      pa->sub[b][r][1] = c1;
      k0 = n0; k1 = n1;
    }
  }
}

// ---------------------------------------------------------------------------
// Pre-pack kernel: g_pack[b][i] = (x, y, z, sn); also resets handshake flags
// ---------------------------------------------------------------------------
__global__ __launch_bounds__(1024, 1)
void prepack_kernel(const float* __restrict__ pos) {
  const int b = blockIdx.x;
  if (threadIdx.x == 0) { g_prog[b] = 0; g_permdone[b] = 0; }
  const float* px = pos + (size_t)b * 3 * NN;
  const float* py = px + NN;
  const float* pz = px + 2 * NN;
  for (int i = threadIdx.x; i < NN; i += 1024) {
    float xx = px[i], yy = py[i], zz = pz[i];
    float sn = __fadd_rn(__fadd_rn(__fmul_rn(xx, xx), __fmul_rn(yy, yy)),
                         __fmul_rn(zz, zz));
    g_pack[b * NN + i] = make_float4(xx, yy, zz, sn);
  }
}

// ---------------------------------------------------------------------------
// merge16: exact 16-smallest of {cur (distributed), cand (distributed)}
// ---------------------------------------------------------------------------
__device__ __forceinline__ void merge16(unsigned long long& cur,
                                        unsigned long long cand,
                                        unsigned long long* top,
                                        float& tauf, int lane) {
#pragma unroll
  for (int r = 0; r < KNNK; ++r) {
    unsigned long long m = (cur < cand) ? cur : cand;
#pragma unroll
    for (int off = 16; off; off >>= 1) {
      unsigned long long o = __shfl_xor_sync(0xffffffffu, m, off);
      m = (o < m) ? o : m;
    }
    top[r] = m;
    if (cur == m) cur = INF64;
    else if (cand == m) cand = INF64;
  }
  cur = (lane < KNNK) ? top[lane] : INF64;
  unsigned long long t15 = top[15];
  if (t15 == INF64) {
    tauf = __int_as_float(0x7f800000);
  } else {
    uint32_t v = (uint32_t)(t15 >> 32);
    uint32_t bits = (v & 0x80000000u) ? (v ^ 0x80000000u) : ~v;
    tauf = __uint_as_float(bits);
  }
}

// ---------------------------------------------------------------------------
// Mega-kernel: blocks 0..7 FPS, 8..15 perm, 16.. knn (pipelined consumers)
// ---------------------------------------------------------------------------
#define SMEM_FUSED (3 * NN * 4 + 4 * 32 * 4 + 64)

__global__ __launch_bounds__(FT)
void fused_kernel(const float* __restrict__ pos, const float* __restrict__ x,
                  float* __restrict__ out, FpsArgs fargs, PermArgs pargs) {
  extern __shared__ char smem_raw[];
  const int tid = threadIdx.x;

  if (blockIdx.x < BB) {
    // ===================== FPS (producer) =====================
    const int b = blockIdx.x;
    float* sax = (float*)smem_raw;
    float* say = sax + NN;
    float* saz = say + NN;
    uint32_t* swval = (uint32_t*)(saz + NN);   // [2][8]
    uint32_t* swidx = swval + 32;              // [2][8]

    const float* px = pos + (size_t)b * 3 * NN;
    const float* py = px + NN;
    const float* pz = px + 2 * NN;

    unsigned long long rx2[16], ry2[16], rz2[16];
    float rd[32];
#pragma unroll
    for (int j = 0; j < 16; j++) {
      int i0 = (2 * j) * FT + tid;
      int i1 = i0 + FT;
      float x0 = px[i0], x1 = px[i1];
      float y0 = py[i0], y1 = py[i1];
      float z0 = pz[i0], z1 = pz[i1];
      rx2[j] = f2_pack(x0, x1);
      ry2[j] = f2_pack(y0, y1);
      rz2[j] = f2_pack(z0, z1);
      sax[i0] = x0; sax[i1] = x1;
      say[i0] = y0; say[i1] = y1;
      saz[i0] = z0; saz[i1] = z1;
      rd[2 * j] = 1e10f; rd[2 * j + 1] = 1e10f;
    }
    __syncthreads();

    const int start = fargs.start[b];
    if (tid == 0) g_idx[b * MM] = start;
    float bx = sax[start], by = say[start], bz = saz[start];

    const int lane = tid & 31, warp = tid >> 5;
    int par = 0;

    for (int it = 1; it < FPS_M; ++it) {
      unsigned long long nbx2 = f2_pack(-bx, -bx);
      unsigned long long nby2 = f2_pack(-by, -by);
      unsigned long long nbz2 = f2_pack(-bz, -bz);

      float bestv = -1.0f;
#pragma unroll
      for (int j = 0; j < 16; j++) {
        unsigned long long dx2 = f2_add(rx2[j], nbx2);
        unsigned long long dy2 = f2_add(ry2[j], nby2);
        unsigned long long dz2 = f2_add(rz2[j], nbz2);
        unsigned long long dd2 =
            f2_add(f2_add(f2_mul(dx2, dx2), f2_mul(dy2, dy2)), f2_mul(dz2, dz2));
        float d0, d1;
        f2_unpack(dd2, &d0, &d1);
        float nv0 = fminf(rd[2 * j], d0);
        rd[2 * j] = nv0;
        float nv1 = fminf(rd[2 * j + 1], d1);
        rd[2 * j + 1] = nv1;
        bestv = fmaxf(bestv, fmaxf(nv0, nv1));
      }
      // epilogue: first (lowest global index) slot equal to bestv
      int besti = 0x7FFFFFFF;
#pragma unroll
      for (int j = 0; j < 32; j++) {
        int gi = j * FT + tid;
        besti = (rd[j] == bestv) ? min(besti, gi) : besti;
      }
      uint32_t bits = __float_as_uint(bestv);
      uint32_t wmax = __reduce_max_sync(0xffffffffu, bits);
      uint32_t cand = (bits == wmax) ? (uint32_t)besti : 0xFFFFFFFFu;
      uint32_t wi   = __reduce_min_sync(0xffffffffu, cand);
      if (lane == 0) { swval[par * 8 + warp] = wmax; swidx[par * 8 + warp] = wi; }
      __syncthreads();
      uint32_t v    = (lane < 8) ? swval[par * 8 + lane] : 0u;
      uint32_t bmax = __reduce_max_sync(0xffffffffu, v);
      uint32_t bc   = (lane < 8 && v == bmax) ? swidx[par * 8 + lane] : 0xFFFFFFFFu;
      uint32_t w    = __reduce_min_sync(0xffffffffu, bc);
      if (tid == 0) {
        g_idx[b * MM + it] = (int)w;
        if ((it & 15) == 0) {               // publish progress (release)
          __threadfence();
          g_prog[b] = it + 1;
        }
      }
      bx = sax[w]; by = say[w]; bz = saz[w];
      par ^= 1;
    }
    if (tid == 0) { __threadfence(); g_prog[b] = FPS_M; }
  } else if (blockIdx.x < 2 * BB) {
    // ===================== random-permutation tail (producer) ===============
    const int b = blockIdx.x - BB;
    unsigned long long* A = (unsigned long long*)smem_raw;

    for (int r = 0; r < 2; ++r) {
      const uint32_t k0 = pargs.sub[b][r][0];
      const uint32_t k1 = pargs.sub[b][r][1];
#pragma unroll 4
      for (int t = 0; t < 32; ++t) {
        int i = tid + t * FT;
        uint32_t y0, y1;
        threefry2x32(k0, k1, 0u, (uint32_t)i, &y0, &y1);
        uint32_t kk = y0 ^ y1;
        uint32_t v = (r == 0) ? (uint32_t)i : (uint32_t)(A[i] & 0x1FFFull);
        A[i] = ((unsigned long long)kk << 32) |
               ((unsigned long long)(uint32_t)i << 13) | v;
      }
      __syncthreads();
      for (int kk2 = 2; kk2 <= NN; kk2 <<= 1) {
        for (int jj = kk2 >> 1; jj > 0; jj >>= 1) {
#pragma unroll 4
          for (int t = 0; t < 32; ++t) {
            int i = tid + t * FT;
            int ixj = i ^ jj;
            if (ixj > i) {
              bool up = ((i & kk2) == 0);
              unsigned long long a = A[i], c = A[ixj];
              if ((a > c) == up) { A[i] = c; A[ixj] = a; }
            }
          }
          __syncthreads();
        }
      }
    }
    for (int t = tid; t < RAND_M; t += FT)
      g_idx[b * MM + FPS_M + t] = (int)(A[t] & 0x1FFFull);
    __syncthreads();
    if (tid == 0) { __threadfence(); g_permdone[b] = 1; }
  } else {
    // ===================== knn (consumer) =====================
    // batch-minor mapping so the in-order block window tracks all 8 frontiers
    const int kb = blockIdx.x - 2 * BB;
    const int b  = kb & 7;
    const int c0 = (kb >> 3) << 3;            // first center of this block
    const int warp = tid >> 5, lane = tid & 31;
    const int ci = c0 + warp;

    // wait until our centers exist
    if (tid == 0) {
      if (c0 < FPS_M) {
        const int need = min(c0 + 8, FPS_M);
        while (g_prog[b] < need) __nanosleep(256);
      }
      if (c0 + 8 > FPS_M) {
        while (g_permdone[b] == 0) __nanosleep(256);
      }
    }
    __syncthreads();

    float4* spt = (float4*)smem_raw;                         // 32 KB tile
    unsigned long long* sbufall = (unsigned long long*)(smem_raw + 2048 * 16);
    unsigned long long* buf = sbufall + warp * 64;

    const float* px = pos + (size_t)b * 3 * NN;
    const float4* pk = g_pack + (size_t)b * NN;

    const int cidx = __ldcg(&g_idx[b * MM + ci]);            // L2 (fresh) read
    const float4 cc = pk[cidx];
    const float sx = cc.x, sy = cc.y, sz = cc.z, sm = cc.w;

    unsigned long long top[KNNK];
    unsigned long long cur = INF64;
    float tauf = __int_as_float(0x7f800000);

    int base = 0;
    const uint32_t ltmask = (lane == 31) ? 0x7FFFFFFFu : ((1u << lane) - 1u);

    for (int tile = 0; tile < 4; ++tile) {
      __syncthreads();
      const int tbase = tile * 2048;
#pragma unroll
      for (int t = 0; t < 8; ++t)
        spt[tid + t * 256] = pk[tbase + tid + t * 256];
      __syncthreads();

      int s0 = 0;
      if (tile == 0) {
        float4 p = spt[lane];
        float dot = __fadd_rn(
            __fadd_rn(__fmul_rn(sx, p.x), __fmul_rn(sy, p.y)), __fmul_rn(sz, p.z));
        float d2 = __fsub_rn(__fadd_rn(sm, p.w), __fmul_rn(2.0f, dot));
        cur = ((unsigned long long)f2ord(d2) << 32) | (uint32_t)lane;
        merge16(cur, INF64, top, tauf, lane);
        s0 = 1;
      }
#pragma unroll 2
      for (int s = s0; s < 64; ++s) {
        const int li = (s << 5) | lane;
        float4 p = spt[li];
        float dot = __fadd_rn(
            __fadd_rn(__fmul_rn(sx, p.x), __fmul_rn(sy, p.y)), __fmul_rn(sz, p.z));
        float d2 = __fsub_rn(__fadd_rn(sm, p.w), __fmul_rn(2.0f, dot));
        bool pred = (d2 <= tauf);
        uint32_t mask = __ballot_sync(0xffffffffu, pred);
        if (mask) {
          int pre = __popc(mask & ltmask);
          if (pred)
            buf[base + pre] =
                ((unsigned long long)f2ord(d2) << 32) | (uint32_t)(tbase + li);
          base += __popc(mask);
          __syncwarp();
          while (base >= 32) {
            unsigned long long cand = buf[lane];
            merge16(cur, cand, top, tauf, lane);
            base -= 32;
            unsigned long long t = (lane < base) ? buf[32 + lane] : 0ull;
            __syncwarp();
            if (lane < base) buf[lane] = t;
            __syncwarp();
          }
        }
      }
    }
    if (base > 0) {
      __syncwarp();
      unsigned long long cand = (lane < base) ? buf[lane] : INF64;
      merge16(cur, cand, top, tauf, lane);
    }

    // softmax over exact euclidean distances (same ops as reference)
    int   id[KNNK];
    float w[KNNK];
    float maxl = -3.4e38f;
#pragma unroll
    for (int k = 0; k < KNNK; k++) {
      id[k] = (int)(top[k] & 0xFFFFFFFFull);
      float dx = px[id[k]] - sx, dy = px[NN + id[k]] - sy,
            dz = px[2 * NN + id[k]] - sz;
      float dn = sqrtf(dx * dx + dy * dy + dz * dz);
      dn = fmaxf(dn, 1e-6f);
      float l = -dn / 0.2f;
      w[k] = l;
      maxl = fmaxf(maxl, l);
    }
    float s = 0.0f;
#pragma unroll
    for (int k = 0; k < KNNK; k++) { w[k] = expf(w[k] - maxl); s += w[k]; }
    float inv = 1.0f / s;
#pragma unroll
    for (int k = 0; k < KNNK; k++) w[k] *= inv;

    if (lane == 0) {
      float* outpos = out + (size_t)BB * CC * MM;
      outpos[(size_t)b * 3 * MM + ci] = sx;
      outpos[(size_t)b * 3 * MM + MM + ci] = sy;
      outpos[(size_t)b * 3 * MM + 2 * MM + ci] = sz;
    }

    const float* xb = x + (size_t)b * CC * NN;
    const float* r0 = xb + (size_t)lane * NN;
    const float* r1 = xb + (size_t)(lane + 32) * NN;
    float acc0 = 0.0f, acc1 = 0.0f;
#pragma unroll
    for (int k = 0; k < KNNK; k++) {
      acc0 += w[k] * r0[id[k]];
      acc1 += w[k] * r1[id[k]];
    }
    out[((size_t)b * CC + lane) * MM + ci] = acc0;
    out[((size_t)b * CC + lane + 32) * MM + ci] = acc1;
  }
}

// ---------------------------------------------------------------------------
extern "C" void kernel_launch(void* const* d_in, const int* in_sizes, int n_in,
                              void* d_out, int out_size) {
  const float* x   = (const float*)d_in[0];
  const float* pos = (const float*)d_in[1];
  (void)in_sizes; (void)n_in; (void)out_size;

  FpsArgs fa;
  PermArgs pa;
  compute_consts(&fa, &pa);

  cudaFuncSetAttribute(fused_kernel,
                       cudaFuncAttributeMaxDynamicSharedMemorySize, SMEM_FUSED);

  prepack_kernel<<<BB, 1024>>>(pos);
  fused_kernel<<<2 * BB + KNB, FT, SMEM_FUSED>>>(pos, x, (float*)d_out, fa, pa);
}

// round 15
// speedup vs baseline: 1.3333x; 1.3333x over previous
#include <cuda_runtime.h>
#include <cstdint>
#include <math.h>

// Problem constants (shapes are fixed by the dataset)
#define BB 8
#define CC 64
#define NN 8192
#define MM 2048
#define KNNK 16
#define FPS_M 1433   // int(2048 * 0.7)
#define RAND_M 615   // 2048 - 1433

#define FT 256               // fused kernel block size (8 warps)
#define INF64 0xFFFFFFFFFFFFFFFFull
#define FULLM 0xffffffffu

// ---------------------------------------------------------------------------
// Threefry-2x32 core (jax threefry2x32 primitive)
// ---------------------------------------------------------------------------
__host__ __device__ __forceinline__ void threefry2x32(
    uint32_t k0, uint32_t k1, uint32_t c0, uint32_t c1,
    uint32_t* o0, uint32_t* o1) {
  uint32_t ks2 = 0x1BD11BDAu ^ k0 ^ k1;
  uint32_t x0 = c0 + k0;
  uint32_t x1 = c1 + k1;
#define TF_ROTL(v, r) (((v) << (r)) | ((v) >> (32 - (r))))
#define TF_ROUND(r) do { x0 += x1; x1 = TF_ROTL(x1, r); x1 ^= x0; } while (0)
  TF_ROUND(13); TF_ROUND(15); TF_ROUND(26); TF_ROUND(6);
  x0 += k1; x1 += ks2 + 1u;
  TF_ROUND(17); TF_ROUND(29); TF_ROUND(16); TF_ROUND(24);
  x0 += ks2; x1 += k0 + 2u;
  TF_ROUND(13); TF_ROUND(15); TF_ROUND(26); TF_ROUND(6);
  x0 += k0; x1 += k1 + 3u;
  TF_ROUND(17); TF_ROUND(29); TF_ROUND(16); TF_ROUND(24);
  x0 += k1; x1 += ks2 + 4u;
  TF_ROUND(13); TF_ROUND(15); TF_ROUND(26); TF_ROUND(6);
  x0 += ks2; x1 += k0 + 5u;
#undef TF_ROUND
#undef TF_ROTL
  *o0 = x0; *o1 = x1;
}

struct FpsArgs  { int start[BB]; };
struct PermArgs { uint32_t sub[BB][2][2]; };

__device__ int g_idx[BB * MM];
__device__ float4 g_pack[BB * NN];   // (x, y, z, ||p||^2) per point

// ---------------------------------------------------------------------------
// Packed f32x2 helpers (bit-exact per-lane .rn semantics, sm_103a)
// ---------------------------------------------------------------------------
__device__ __forceinline__ unsigned long long f2_pack(float lo, float hi) {
  unsigned long long o;
  asm("mov.b64 %0, {%1, %2};" : "=l"(o) : "f"(lo), "f"(hi));
  return o;
}
__device__ __forceinline__ void f2_unpack(unsigned long long v, float* lo, float* hi) {
  asm("mov.b64 {%0, %1}, %2;" : "=f"(*lo), "=f"(*hi) : "l"(v));
}
__device__ __forceinline__ unsigned long long f2_add(unsigned long long a,
                                                     unsigned long long b) {
  unsigned long long o;
  asm("add.rn.f32x2 %0, %1, %2;" : "=l"(o) : "l"(a), "l"(b));
  return o;
}
__device__ __forceinline__ unsigned long long f2_mul(unsigned long long a,
                                                     unsigned long long b) {
  unsigned long long o;
  asm("mul.rn.f32x2 %0, %1, %2;" : "=l"(o) : "l"(a), "l"(b));
  return o;
}

// monotone map: float bits -> u32 preserving float ordering (handles negatives)
__device__ __forceinline__ uint32_t f2ord(float f) {
  uint32_t u = __float_as_uint(f);
  return u ^ ((u & 0x80000000u) ? 0xFFFFFFFFu : 0x80000000u);
}

// ---------------------------------------------------------------------------
// Host-side PRNG derivation — PARTITIONABLE threefry semantics
// ---------------------------------------------------------------------------
static void compute_consts(FpsArgs* fa, PermArgs* pa) {
  for (int b = 0; b < BB; b++) {
    uint32_t fk0, fk1;
    threefry2x32(0u, 42u, 0u, (uint32_t)b, &fk0, &fk1);
    uint32_t k20, k21;
    threefry2x32(fk0, fk1, 0u, 1u, &k20, &k21);
    uint32_t s0, s1;
    threefry2x32(k20, k21, 0u, 0u, &s0, &s1);
    fa->start[b] = (int)((s0 ^ s1) & (NN - 1));
  }
  uint32_t rk0, rk1;
  threefry2x32(0u, 42u, 0u, 1u, &rk0, &rk1);
  for (int b = 0; b < BB; b++) {
    uint32_t k0, k1;
    threefry2x32(rk0, rk1, 0u, (uint32_t)b, &k0, &k1);
    for (int r = 0; r < 2; r++) {
      uint32_t n0, n1, c0, c1;
      threefry2x32(k0, k1, 0u, 0u, &n0, &n1);
      threefry2x32(k0, k1, 0u, 1u, &c0, &c1);
      pa->sub[b][r][0] = c0;
      pa->sub[b][r][1] = c1;
      k0 = n0; k1 = n1;
    }
  }
}

// ---------------------------------------------------------------------------
// Pre-pack kernel: g_pack[b][i] = (x, y, z, sn) with sn in reference op-order
// ---------------------------------------------------------------------------
__global__ __launch_bounds__(1024, 1)
void prepack_kernel(const float* __restrict__ pos) {
  const int b = blockIdx.x;
  const float* px = pos + (size_t)b * 3 * NN;
  const float* py = px + NN;
  const float* pz = px + 2 * NN;
  for (int i = threadIdx.x; i < NN; i += 1024) {
    float xx = px[i], yy = py[i], zz = pz[i];
    float sn = __fadd_rn(__fadd_rn(__fmul_rn(xx, xx), __fmul_rn(yy, yy)),
                         __fmul_rn(zz, zz));
    g_pack[b * NN + i] = make_float4(xx, yy, zz, sn);
  }
}

// Fused FPS + permutation kernel — R12-exact (measured ~610 us)
#define SMEM_FUSED (3 * NN * 4 + 4 * 32 * 4 + 64)

__global__ __launch_bounds__(FT, 1)
void fused_kernel(const float* __restrict__ pos, FpsArgs fargs, PermArgs pargs) {
  extern __shared__ char smem_raw[];
  const int tid = threadIdx.x;

  if (blockIdx.x < BB) {
    const int b = blockIdx.x;
    float* sax = (float*)smem_raw;
    float* say = sax + NN;
    float* saz = say + NN;
    uint32_t* swval = (uint32_t*)(saz + NN);   // [2][8]
    uint32_t* swidx = swval + 32;              // [2][8]

    const float* px = pos + (size_t)b * 3 * NN;
    const float* py = px + NN;
    const float* pz = px + 2 * NN;

    unsigned long long rx2[16], ry2[16], rz2[16];
    float rd[32];
#pragma unroll
    for (int j = 0; j < 16; j++) {
      int i0 = (2 * j) * FT + tid;
      int i1 = i0 + FT;
      float x0 = px[i0], x1 = px[i1];
      float y0 = py[i0], y1 = py[i1];
      float z0 = pz[i0], z1 = pz[i1];
      rx2[j] = f2_pack(x0, x1);
      ry2[j] = f2_pack(y0, y1);
      rz2[j] = f2_pack(z0, z1);
      sax[i0] = x0; sax[i1] = x1;
      say[i0] = y0; say[i1] = y1;
      saz[i0] = z0; saz[i1] = z1;
      rd[2 * j] = 1e10f; rd[2 * j + 1] = 1e10f;
    }
    __syncthreads();

    const int start = fargs.start[b];
    if (tid == 0) g_idx[b * MM] = start;
    float bx = sax[start], by = say[start], bz = saz[start];

    const int lane = tid & 31, warp = tid >> 5;
    int par = 0;

    for (int it = 1; it < FPS_M; ++it) {
      unsigned long long nbx2 = f2_pack(-bx, -bx);
      unsigned long long nby2 = f2_pack(-by, -by);
      unsigned long long nbz2 = f2_pack(-bz, -bz);

      float bestv = -1.0f;
#pragma unroll
      for (int j = 0; j < 16; j++) {
        unsigned long long dx2 = f2_add(rx2[j], nbx2);
        unsigned long long dy2 = f2_add(ry2[j], nby2);
        unsigned long long dz2 = f2_add(rz2[j], nbz2);
        unsigned long long dd2 =
            f2_add(f2_add(f2_mul(dx2, dx2), f2_mul(dy2, dy2)), f2_mul(dz2, dz2));
        float d0, d1;
        f2_unpack(dd2, &d0, &d1);
        float nv0 = fminf(rd[2 * j], d0);
        rd[2 * j] = nv0;
        float nv1 = fminf(rd[2 * j + 1], d1);
        rd[2 * j + 1] = nv1;
        bestv = fmaxf(bestv, fmaxf(nv0, nv1));
      }
      int besti = 0x7FFFFFFF;
#pragma unroll
      for (int j = 0; j < 32; j++) {
        int gi = j * FT + tid;
        besti = (rd[j] == bestv) ? min(besti, gi) : besti;
      }
      uint32_t bits = __float_as_uint(bestv);
      uint32_t wmax = __reduce_max_sync(FULLM, bits);
      uint32_t cand = (bits == wmax) ? (uint32_t)besti : 0xFFFFFFFFu;
      uint32_t wi   = __reduce_min_sync(FULLM, cand);
      if (lane == 0) { swval[par * 8 + warp] = wmax; swidx[par * 8 + warp] = wi; }
      __syncthreads();
      uint32_t v    = (lane < 8) ? swval[par * 8 + lane] : 0u;
      uint32_t bmax = __reduce_max_sync(FULLM, v);
      uint32_t bc   = (lane < 8 && v == bmax) ? swidx[par * 8 + lane] : 0xFFFFFFFFu;
      uint32_t w    = __reduce_min_sync(FULLM, bc);
      if (tid == 0) g_idx[b * MM + it] = (int)w;
      bx = sax[w]; by = say[w]; bz = saz[w];
      par ^= 1;
    }
  } else {
    const int b = blockIdx.x - BB;
    unsigned long long* A = (unsigned long long*)smem_raw;

    for (int r = 0; r < 2; ++r) {
      const uint32_t k0 = pargs.sub[b][r][0];
      const uint32_t k1 = pargs.sub[b][r][1];
#pragma unroll 4
      for (int t = 0; t < 32; ++t) {
        int i = tid + t * FT;
        uint32_t y0, y1;
        threefry2x32(k0, k1, 0u, (uint32_t)i, &y0, &y1);
        uint32_t kk = y0 ^ y1;
        uint32_t v = (r == 0) ? (uint32_t)i : (uint32_t)(A[i] & 0x1FFFull);
        A[i] = ((unsigned long long)kk << 32) |
               ((unsigned long long)(uint32_t)i << 13) | v;
      }
      __syncthreads();
      for (int kk2 = 2; kk2 <= NN; kk2 <<= 1) {
        for (int jj = kk2 >> 1; jj > 0; jj >>= 1) {
#pragma unroll 4
          for (int t = 0; t < 32; ++t) {
            int i = tid + t * FT;
            int ixj = i ^ jj;
            if (ixj > i) {
              bool up = ((i & kk2) == 0);
              unsigned long long a = A[i], c = A[ixj];
              if ((a > c) == up) { A[i] = c; A[ixj] = a; }
            }
          }
          __syncthreads();
        }
      }
    }
    for (int t = tid; t < RAND_M; t += FT)
      g_idx[b * MM + FPS_M + t] = (int)(A[t] & 0x1FFFull);
  }
}

// ---------------------------------------------------------------------------
// merge16 v2: exact 16-smallest of {cur, cand} (both lane-distributed),
// result DISTRIBUTED: lane r ends holding the r-th smallest (no top[] array).
// Keys unique (idx embedded). Rebuilds tauf from lane 15.
// ---------------------------------------------------------------------------
__device__ __forceinline__ void merge16v2(unsigned long long& cur,
                                          unsigned long long cand,
                                          float& tauf, int lane) {
  unsigned long long nc = INF64;
#pragma unroll
  for (int r = 0; r < KNNK; ++r) {
    unsigned long long m = (cur < cand) ? cur : cand;
#pragma unroll
    for (int off = 16; off; off >>= 1) {
      unsigned long long o = __shfl_xor_sync(FULLM, m, off);
      m = (o < m) ? o : m;
    }
    if (lane == r) nc = m;
    if (cur == m) cur = INF64;
    else if (cand == m) cand = INF64;
  }
  cur = nc;
  unsigned long long t15 = __shfl_sync(FULLM, nc, 15);
  if (t15 == INF64) {
    tauf = __int_as_float(0x7f800000);
  } else {
    uint32_t v = (uint32_t)(t15 >> 32);
    uint32_t bits = (v & 0x80000000u) ? (v ^ 0x80000000u) : ~v;
    tauf = __uint_as_float(bits);
  }
}

// ---------------------------------------------------------------------------
// KNN v5: warp-per-center, lane-distributed top-16, occ-4 (<=64 regs)
// ---------------------------------------------------------------------------
__global__ __launch_bounds__(256, 4)
void knn_kernel(const float* __restrict__ x, const float* __restrict__ pos,
                float* __restrict__ out) {
  __shared__ float4 spt[2048];                 // 32 KB point tile
  __shared__ unsigned long long sbuf[8][64];   // qualifier buffers
  const int warp = threadIdx.x >> 5, lane = threadIdx.x & 31;
  const int b  = blockIdx.x >> 8;
  const int ci = ((blockIdx.x & 255) << 3) + warp;
  const float* px = pos + (size_t)b * 3 * NN;
  const float4* pk = g_pack + (size_t)b * NN;

  const int cidx = g_idx[b * MM + ci];
  const float4 cc = pk[cidx];
  const float sx = cc.x, sy = cc.y, sz = cc.z, sm = cc.w;

  unsigned long long cur = INF64;
  float tauf = __int_as_float(0x7f800000);

  unsigned long long* buf = sbuf[warp];
  int base = 0;
  const uint32_t ltmask = (lane == 31) ? 0x7FFFFFFFu : ((1u << lane) - 1u);

  for (int tile = 0; tile < 4; ++tile) {
    __syncthreads();
    const int tbase = tile * 2048;
#pragma unroll
    for (int t = 0; t < 8; ++t)
      spt[threadIdx.x + t * 256] = pk[tbase + threadIdx.x + t * 256];
    __syncthreads();

    int s0 = 0;
    if (tile == 0) {
      float4 p = spt[lane];
      float dot = __fadd_rn(
          __fadd_rn(__fmul_rn(sx, p.x), __fmul_rn(sy, p.y)), __fmul_rn(sz, p.z));
      float d2 = __fsub_rn(__fadd_rn(sm, p.w), __fmul_rn(2.0f, dot));
      cur = ((unsigned long long)f2ord(d2) << 32) | (uint32_t)lane;
      merge16v2(cur, INF64, tauf, lane);
      s0 = 1;
    }
#pragma unroll 2
    for (int s = s0; s < 64; ++s) {
      const int li = (s << 5) | lane;
      float4 p = spt[li];
      float dot = __fadd_rn(
          __fadd_rn(__fmul_rn(sx, p.x), __fmul_rn(sy, p.y)), __fmul_rn(sz, p.z));
      float d2 = __fsub_rn(__fadd_rn(sm, p.w), __fmul_rn(2.0f, dot));
      bool pred = (d2 <= tauf);
      uint32_t mask = __ballot_sync(FULLM, pred);
      if (mask) {
        int pre = __popc(mask & ltmask);
        if (pred)
          buf[base + pre] =
              ((unsigned long long)f2ord(d2) << 32) | (uint32_t)(tbase + li);
        base += __popc(mask);
        __syncwarp();
        while (base >= 32) {
          unsigned long long cand = buf[lane];
          merge16v2(cur, cand, tauf, lane);
          base -= 32;
          unsigned long long t = (lane < base) ? buf[32 + lane] : 0ull;
          __syncwarp();
          if (lane < base) buf[lane] = t;
          __syncwarp();
        }
      }
    }
  }
  if (base > 0) {
    __syncwarp();
    unsigned long long cand = (lane < base) ? buf[lane] : INF64;
    merge16v2(cur, cand, tauf, lane);
  }

  // Epilogue: lane k (k<16) holds the k-th neighbor. Per-lane distance/weight;
  // softmax max exact, sums via butterfly (fp-order within tolerance).
  const int myid = (lane < KNNK) ? (int)(cur & 0xFFFFFFFFull) : 0;
  float dx = px[myid] - sx, dy = px[NN + myid] - sy, dz = px[2 * NN + myid] - sz;
  float dn = sqrtf(dx * dx + dy * dy + dz * dz);
  dn = fmaxf(dn, 1e-6f);
  float l = -dn / 0.2f;

  float lm = (lane < KNNK) ? l : -3.4e38f;
#pragma unroll
  for (int off = 16; off; off >>= 1)
    lm = fmaxf(lm, __shfl_xor_sync(FULLM, lm, off));
  float e = (lane < KNNK) ? expf(l - lm) : 0.0f;
  float ssum = e;
#pragma unroll
  for (int off = 16; off; off >>= 1)
    ssum += __shfl_xor_sync(FULLM, ssum, off);
  float wgt = e / ssum;

  if (lane == 0) {
    float* outpos = out + (size_t)BB * CC * MM;
    outpos[(size_t)b * 3 * MM + ci] = sx;
    outpos[(size_t)b * 3 * MM + MM + ci] = sy;
    outpos[(size_t)b * 3 * MM + 2 * MM + ci] = sz;
  }

  const float* xb = x + (size_t)b * CC * NN;
  const float* r0 = xb + (size_t)lane * NN;
  const float* r1 = xb + (size_t)(lane + 32) * NN;
  float acc0 = 0.0f, acc1 = 0.0f;
#pragma unroll
  for (int k = 0; k < KNNK; k++) {
    int   idk = __shfl_sync(FULLM, myid, k);
    float wk  = __shfl_sync(FULLM, wgt, k);
    acc0 += wk * r0[idk];
    acc1 += wk * r1[idk];
  }
  out[((size_t)b * CC + lane) * MM + ci] = acc0;
  out[((size_t)b * CC + lane + 32) * MM + ci] = acc1;
}

// ---------------------------------------------------------------------------
extern "C" void kernel_launch(void* const* d_in, const int* in_sizes, int n_in,
                              void* d_out, int out_size) {
  const float* x   = (const float*)d_in[0];
  const float* pos = (const float*)d_in[1];
  (void)in_sizes; (void)n_in; (void)out_size;

  FpsArgs fa;
  PermArgs pa;
  compute_consts(&fa, &pa);

  cudaFuncSetAttribute(fused_kernel,
                       cudaFuncAttributeMaxDynamicSharedMemorySize, SMEM_FUSED);

  prepack_kernel<<<BB, 1024>>>(pos);
  fused_kernel<<<2 * BB, FT, SMEM_FUSED>>>(pos, fa, pa);
  knn_kernel<<<BB * 256, 256>>>(x, pos, (float*)d_out);
}